// round 12
// baseline (speedup 1.0000x reference)
#include <cuda_runtime.h>
#include <cuda_bf16.h>
#include <cstdint>

#define N_ROIS   32768
#define N_GT     1024
#define N_IMAGES 8
#define NT       512
#define NB       296                 // 2 blocks per SM, single wave
#define NGT_PAD  1152

// approx-rcp IoU argmax step (comparisons only); ag from sarea
#define IOU_STEP(J, BB, BJ) {                                   \
    float4 g  = sbox[J];                                        \
    float ag  = sarea[J];                                       \
    float iw  = fminf(rx2p, g.z) - fmaxf(rx1, g.x);             \
    float ih  = fminf(ry2p, g.w) - fmaxf(ry1, g.y);             \
    float inter = fmaxf(iw, 0.0f) * ih;                         \
    float uni = (area_r + ag) - inter;                          \
    float iouv = __fdividef(inter, uni);                        \
    bool better = iouv > (BB);                                  \
    BB = better ? iouv : (BB);                                  \
    BJ = better ? (J)  : (BJ);                                  \
}

// merge: greater iou wins; exact tie -> smaller j (sentinel -1 never wins ties)
#define MERGE(OB, OJ) {                                         \
    bool take = ((OB) > best) ||                                \
        ((OB) == best && (unsigned)(OJ) < (unsigned)bj);        \
    best = take ? (OB) : best;                                  \
    bj   = take ? (OJ) : bj;                                    \
}

__global__ void __launch_bounds__(NT, 2) roitarget_fused(const float* __restrict__ rois,
                                                         const int* __restrict__ rb,
                                                         const float* __restrict__ gt,
                                                         const int* __restrict__ gb,
                                                         float* __restrict__ out) {
    __shared__ float  sgt[5 * N_GT];       // 20KB raw staged gt (coalesced)
    __shared__ float4 sbox[NGT_PAD];       // 18.4KB compacted x1,y1,x2+1,y2+1 (+pads)
    __shared__ float  sarea[NGT_PAD];      // 4.6KB areas (+pads)
    __shared__ float  slab[NGT_PAD];       // 4.6KB labels
    __shared__ float4 sroi[128];           // 2KB ROI coords by local index
    __shared__ int    sgcnt[32][9];        // per-chunk per-batch GT counts (padded)
    __shared__ int    sexcl[32][9];        // exclusive chunk prefix (padded)
    __shared__ int    stot[N_IMAGES];
    __shared__ int    soff[N_IMAGES + 1];  // PADDED batch offsets
    __shared__ int    snf[N_IMAGES];       // per-batch group count (padded len / 16)
    __shared__ int    swc[4][8];           // ROI counts per warp/batch
    __shared__ int    wbase[4][8];
    __shared__ int    sprovb[128], sprovr[128];
    __shared__ int    ssrc[128];           // sorted pos -> local ROI index
    __shared__ int    ssb[128];            // sorted pos -> batch

    const int tid  = threadIdx.x;
    const int w    = tid >> 5;
    const int lane = tid & 31;
    const unsigned lt = (1u << lane) - 1u;

    const int start = (blockIdx.x * N_ROIS) / NB;
    const int next  = ((blockIdx.x + 1) * N_ROIS) / NB;
    const int nroi  = next - start;        // 110 or 111

    // ---- coalesced GT staging + hoisted loads (overlap ballot phase) ----
#pragma unroll
    for (int k = 0; k < 10; k++) sgt[tid + k * NT] = gt[tid + k * NT];
    const int ja = tid, jb = tid + NT;     // chunks w and 16+w
    const int ba  = gb[ja];
    const int bb2 = gb[jb];
    int myb = -1;
    if (tid < nroi) {
        const int i = start + tid;
        myb = rb[i];
        sroi[tid] = make_float4(rois[5*i+0], rois[5*i+1], rois[5*i+2], rois[5*i+3]);
    }

    // ---- ballot counting: GT chunks (all warps, 2 chunks each) ----
    int ranka = 0, rankb = 0;
#pragma unroll
    for (int b = 0; b < N_IMAGES; b++) {
        unsigned ma = __ballot_sync(0xffffffffu, ba == b);
        if (ba == b) ranka = __popc(ma & lt);
        unsigned mb = __ballot_sync(0xffffffffu, bb2 == b);
        if (bb2 == b) rankb = __popc(mb & lt);
        if (lane == 0) { sgcnt[w][b] = __popc(ma); sgcnt[16 + w][b] = __popc(mb); }
    }
    // ---- ballot counting: ROIs (warps 0-3) ----
    if (w < 4) {
        int rank = 0;
#pragma unroll
        for (int b = 0; b < N_IMAGES; b++) {
            unsigned m = __ballot_sync(0xffffffffu, myb == b);
            if (myb == b) rank = __popc(m & lt);
            if (lane == 0) swc[w][b] = __popc(m);
        }
        if (tid < 128) { sprovb[tid] = myb; sprovr[tid] = rank; }
    }
    __syncthreads();                       // sync 1

    // ---- scans in parallel: warps 0-7 GT chunk-scan; warp 8 ROI bases ----
    if (w < N_IMAGES) {
        int v = sgcnt[lane][w];
        int incl = v;
#pragma unroll
        for (int d = 1; d < 32; d <<= 1) {
            int t = __shfl_up_sync(0xffffffffu, incl, d);
            if (lane >= d) incl += t;
        }
        sexcl[lane][w] = incl - v;
        if (lane == 31) stot[w] = incl;
    } else if (w == 8) {
        // single-warp exclusive scan over 32 (batch-major) cells: lane = b*4+w2
        int b2 = lane >> 2, w2 = lane & 3;
        int v = swc[w2][b2];
        int incl = v;
#pragma unroll
        for (int d = 1; d < 32; d <<= 1) {
            int t = __shfl_up_sync(0xffffffffu, incl, d);
            if (lane >= d) incl += t;
        }
        wbase[w2][b2] = incl - v;
    }
    __syncthreads();                       // sync 2

    // ---- per-warp redundant PADDED offsets (identical values; no barrier) ----
    if (lane == 0) {
        int o = 0;
#pragma unroll
        for (int b = 0; b < N_IMAGES; b++) {
            int plen = (stot[b] + 15) & ~15;
            soff[b] = o; snf[b] = plen >> 4; o += plen;
        }
        soff[N_IMAGES] = o;
    }
    __syncwarp();

    // ---- GT parse from staged smem (stride-5 LDS: conflict-free) + scatter ----
    {
        const float x1 = sgt[5*ja+0], y1 = sgt[5*ja+1];
        const float x2 = sgt[5*ja+2], y2 = sgt[5*ja+3], cls = sgt[5*ja+4];
        const int da = soff[ba] + sexcl[w][ba] + ranka;
        sbox[da]  = make_float4(x1, y1, x2 + 1.0f, y2 + 1.0f);
        sarea[da] = ((x2 - x1) + 1.0f) * ((y2 - y1) + 1.0f);
        slab[da]  = cls;

        const float u1 = sgt[5*jb+0], v1 = sgt[5*jb+1];
        const float u2 = sgt[5*jb+2], v2 = sgt[5*jb+3], cl2 = sgt[5*jb+4];
        const int db = soff[bb2] + sexcl[16 + w][bb2] + rankb;
        sbox[db]  = make_float4(u1, v1, u2 + 1.0f, v2 + 1.0f);
        sarea[db] = ((u2 - u1) + 1.0f) * ((v2 - v1) + 1.0f);
        slab[db]  = cl2;
    }
    // ---- write pad entries (never win: inter == 0, uni > 0) ----
    if (tid < 128) {
        const int b = tid >> 4, k = tid & 15;
        const int cnt  = stot[b];
        const int plen = (cnt + 15) & ~15;
        if (k < plen - cnt) {
            const int slot = soff[b] + cnt + k;
            sbox[slot]  = make_float4(3e9f, 0.0f, 1e9f, 1e9f);
            sarea[slot] = 1.0f;
            slab[slot]  = 0.0f;
        }
    }
    // ---- ROI scatter (warps 0-3) ----
    if (tid < nroi) {
        int pb = sprovb[tid];
        int dest = wbase[tid >> 5][pb] + sprovr[tid];
        ssrc[dest] = tid;                  // local index
        ssb[dest]  = pb;
    }
    __syncthreads();                       // sync 3

    // ---------------- Phase 3: 4 threads per ROI, interleaved quarters -----
    const int s = tid >> 2;                // ROI slot 0..127
    const int q = tid & 3;                 // quarter
    const bool valid = (s < nroi);
    const int loc = valid ? ssrc[s] : 0;
    const int b   = valid ? ssb[s]  : 0;

    const float4 rr = sroi[loc];
    const float rx1 = rr.x, ry1 = rr.y;
    const float rx2p = rr.z + 1.0f;
    const float ry2p = rr.w + 1.0f;
    const float ew = (rr.z - rx1) + 1.0f;
    const float eh = (rr.w - ry1) + 1.0f;
    const float area_r = ew * eh;

    const int j0 = soff[b];
    const int nfull = valid ? snf[b] : 0;

    float bb0 = 0.0f; int bj0 = -1;
    float bb1 = 0.0f; int bj1 = -1;
    float bb3 = 0.0f; int bj3 = -1;
    float bb4 = 0.0f; int bj4 = -1;

    int base = j0 + q;
    for (int t = 0; t < nfull; t++, base += 16) {
        IOU_STEP(base + 0,  bb0, bj0);
        IOU_STEP(base + 4,  bb1, bj1);
        IOU_STEP(base + 8,  bb3, bj3);
        IOU_STEP(base + 12, bb4, bj4);
    }

    // in-thread chain merge (ties -> smaller j)
    float best = bb0; int bj = bj0;
    MERGE(bb1, bj1);
    MERGE(bb3, bj3);
    MERGE(bb4, bj4);

    // cross-quarter butterfly merge (all lanes participate; idle slots carry -1)
#pragma unroll
    for (int d = 1; d <= 2; d <<= 1) {
        float ob = __shfl_xor_sync(0xffffffffu, best, d);
        int   oj = __shfl_xor_sync(0xffffffffu, bj, d);
        MERGE(ob, oj);
    }

    if (q == 0 && valid) {
        const bool fg = (bj >= 0) && (best >= 0.5f);
        const int ii = start + loc;

        float lbl = 0.0f, dx = 0.0f, dy = 0.0f, dw = 0.0f, dh = 0.0f, wgt = 0.0f;
        if (fg) {
            float4 g = sbox[bj];
            float gw  = g.z - g.x;             // (x2+1) - x1
            float gh  = g.w - g.y;
            float gcx = g.x + 0.5f * gw;
            float gcy = g.y + 0.5f * gh;
            float ecx = rx1 + 0.5f * ew;
            float ecy = ry1 + 0.5f * eh;
            dx = __fdividef(gcx - ecx, ew);    // 2^-21 rel err << 1e-3 tol
            dy = __fdividef(gcy - ecy, eh);
            dw = __logf(__fdividef(gw, ew));
            dh = __logf(__fdividef(gh, eh));
            lbl = slab[bj];
            wgt = 1.0f;
        }

        // Layout: labels[N] | deltas[N][4] | bbwgts[N][1]
        out[ii] = lbl;
        reinterpret_cast<float4*>(out + N_ROIS)[ii] = make_float4(dx, dy, dw, dh);
        out[N_ROIS * 5 + ii] = wgt;
    }
}

extern "C" void kernel_launch(void* const* d_in, const int* in_sizes, int n_in,
                              void* d_out, int out_size) {
    const float* rois = (const float*)d_in[0];
    const int*   rb   = (const int*)d_in[1];
    const float* gt   = (const float*)d_in[2];
    const int*   gb   = (const int*)d_in[3];
    float* out = (float*)d_out;

    roitarget_fused<<<NB, NT>>>(rois, rb, gt, gb, out);
}